// round 12
// baseline (speedup 1.0000x reference)
#include <cuda_runtime.h>
#include <cuda_fp16.h>
#include <cstdint>

// ---------------------------------------------------------------------------
// GNN_EBM reduced form:
//   out[b] = MLP_T(c100 * r0[b]) + MLP_Y(c101 * r0[b]),
//   r0 = relu(z @ Win^T + bin),  z = [x|t|y], c_i from sigmoid(B)*mask rowsums.
//
// Round-12 (on R11's fp16 fragment path):
//  * BT=32 / grid=64: each block runs TWO 16-row tiles with ONE weight fetch.
//    wA registers reused; tile-1 wB reloads are L1 hits. Halves L2 fragment
//    refetch traffic and amortizes per-block fixed cost. Still 2 barriers.
//  * pack via cvt.rn.f16x2.f32 (__floats2half2_rn).
// ---------------------------------------------------------------------------

#define DX      100
#define DN      102
#define HID     256
#define MH      128
#define BT      32             // batch rows per block (2 x 16-row tiles)
#define NBLK    64
#define BATCH   2048
#define THREADS 1024
#define NCA     7              // stage-A chunks (16 k each)
#define NCB     16             // stage-B chunks

#define ZSW     60             // z row stride in 4B words (conflict-free ldsm)
#define RSW     132            // r0 row stride in words  (conflict-free ldsm)

#define NFRAG_A (32 * NCA * 32)     // 7168
#define NFRAG_B (32 * NCB * 32)     // 16384
#define PREP_FRAG_BLOCKS 184        // ceil((7168+16384)/128)
#define PREP_OUT_BLOCKS  (BATCH / 128)   // 16

__device__ float g_c_s[DN];                          // s[j] = rowsum_j(A)/N
__device__ __align__(16) uint2 g_fA[NFRAG_A];        // [tile][chunk][lane]
__device__ __align__(16) uint2 g_fB[NFRAG_B];        // [br*16+wb][chunk][lane]

__device__ __forceinline__ float sigm(float v) {
    return 1.0f / (1.0f + __expf(-v));
}

__device__ __forceinline__ void mma16(float* c, const uint32_t* a,
                                      uint32_t b0, uint32_t b1) {
    asm volatile(
        "mma.sync.aligned.m16n8k16.row.col.f32.f16.f16.f32 "
        "{%0,%1,%2,%3},{%4,%5,%6,%7},{%8,%9},{%0,%1,%2,%3};"
        : "+f"(c[0]), "+f"(c[1]), "+f"(c[2]), "+f"(c[3])
        : "r"(a[0]), "r"(a[1]), "r"(a[2]), "r"(a[3]), "r"(b0), "r"(b1));
}

__device__ __forceinline__ void ldsm4(uint32_t* r, uint32_t saddr) {
    asm volatile(
        "ldmatrix.sync.aligned.m8n8.x4.shared.b16 {%0,%1,%2,%3}, [%4];"
        : "=r"(r[0]), "=r"(r[1]), "=r"(r[2]), "=r"(r[3]) : "r"(saddr));
}

__device__ __forceinline__ uint32_t smem_u32(const void* p) {
    return (uint32_t)__cvta_generic_to_shared(p);
}

__device__ __forceinline__ uint32_t pack_h2(float v0, float v1) {
    __half2 h = __floats2half2_rn(v0, v1);   // cvt.rn.f16x2.f32
    return *reinterpret_cast<uint32_t*>(&h);
}

// ---------------------------------------------------------------------------
// K1 prep (302 blocks x 128 threads):
//   blocks 0..101  : g_c_s[b]
//   blocks 102..285: fragment-pack weights -> g_fA, g_fB
//   blocks 286..301: out[b] = bT2[0] + bY2[0]
// ---------------------------------------------------------------------------
__global__ __launch_bounds__(128) void prep_kernel(
    const float* __restrict__ B,   const float* __restrict__ Win,
    const float* __restrict__ WT1, const float* __restrict__ WY1,
    const float* __restrict__ bT2, const float* __restrict__ bY2,
    float* __restrict__ out)
{
    const int b = blockIdx.x;
    const int t = threadIdx.x;

    if (b < DN) {
        __shared__ float wsum[4];
        int k = t;
        float v = 0.0f;
        bool valid = (b == DN - 1) ? (k == DN - 2) : (k < DN && k != b);
        if (valid) v = sigm(B[b * DN + k]);
        #pragma unroll
        for (int off = 16; off > 0; off >>= 1)
            v += __shfl_xor_sync(0xFFFFFFFFu, v, off);
        if ((t & 31) == 0) wsum[t >> 5] = v;
        __syncthreads();
        if (t == 0)
            g_c_s[b] = (wsum[0] + wsum[1] + wsum[2] + wsum[3]) / (float)DN;
        return;
    }

    if (b >= DN + PREP_FRAG_BLOCKS) {
        int idx = (b - DN - PREP_FRAG_BLOCKS) * 128 + t;
        if (idx < BATCH) out[idx] = bT2[0] + bY2[0];
        return;
    }

    int fid = (b - DN) * 128 + t;
    if (fid < NFRAG_A) {
        int nt   = fid / (NCA * 32);
        int rem  = fid - nt * (NCA * 32);
        int g    = rem >> 5;
        int lane = rem & 31;
        int h  = 8 * nt + (lane >> 2);
        int k0 = 16 * g + 2 * (lane & 3);
        const float* wr = Win + h * DN;
        float v0 = (k0     < DN) ? wr[k0]     : 0.0f;
        float v1 = (k0 + 1 < DN) ? wr[k0 + 1] : 0.0f;
        float v2 = (k0 + 8 < DN) ? wr[k0 + 8] : 0.0f;
        float v3 = (k0 + 9 < DN) ? wr[k0 + 9] : 0.0f;
        uint2 o;
        o.x = pack_h2(v0, v1);
        o.y = pack_h2(v2, v3);
        g_fA[fid] = o;
        return;
    }

    int fid2 = fid - NFRAG_A;
    if (fid2 < NFRAG_B) {
        int tile = fid2 / (NCB * 32);   // br*16 + wb
        int rem  = fid2 - tile * (NCB * 32);
        int j    = rem >> 5;
        int lane = rem & 31;
        const float* W = (tile >> 4) ? WY1 : WT1;
        int h  = 8 * (tile & 15) + (lane >> 2);
        int k0 = 16 * j + 2 * (lane & 3);
        const float* wr = W + h * HID;
        uint2 o;
        o.x = pack_h2(wr[k0],     wr[k0 + 1]);
        o.y = pack_h2(wr[k0 + 8], wr[k0 + 9]);
        g_fB[fid2] = o;
    }
}

// ---------------------------------------------------------------------------
// K2 fused: 1024 threads (32 warps), BT=32 rows/block (2 tiles of 16).
// Warp w: stage A n-tile = cols [8w, 8w+8); stage B: branch w>>4, cols 8*(w&15).
// ---------------------------------------------------------------------------
__global__ __launch_bounds__(THREADS, 1) void fused_kernel(
    const float* __restrict__ x,   const float* __restrict__ tt,
    const float* __restrict__ yy,  const float* __restrict__ bin,
    const float* __restrict__ bT1, const float* __restrict__ wT2,
    const float* __restrict__ bY1, const float* __restrict__ wY2,
    const float* __restrict__ Bp,
    float* __restrict__ out)
{
    __shared__ __align__(16) uint32_t zh[BT * ZSW];    // [32][ZSW]
    __shared__ __align__(16) uint32_t r0h[BT * RSW];   // [32][RSW]
    __shared__ float accc[2];

    const int t    = threadIdx.x;
    const int w    = t >> 5;
    const int lane = t & 31;
    const int grp  = lane >> 2;
    const int qid  = lane & 3;
    const int b0   = blockIdx.x * BT;

    const int brB = w >> 4;       // stage-B branch (0=T, 1=Y)
    const int wb_ = w & 15;

    // ---- hoist stage-A weights into registers (7 x uint2), reused 2x ----
    uint2 wA[NCA];
    {
        const uint2* fA = g_fA + (w * NCA) * 32 + lane;
        #pragma unroll
        for (int g = 0; g < NCA; g++) wA[g] = __ldg(fA + g * 32);
    }

    if (t < 2) accc[t] = 0.0f;

    // ---- fill z tile (32 rows) as fp16 pairs (pads zero) ----
    for (int idx = t; idx < BT * ZSW; idx += THREADS) {
        int r  = idx / ZSW;
        int kw = idx - r * ZSW;
        int b  = b0 + r;
        float v0 = 0.0f, v1 = 0.0f;
        int k0 = 2 * kw;
        if (k0 < DX)            v0 = x[b * DX + k0];
        else if (k0 == DX)      v0 = tt[b];
        else if (k0 == DX + 1)  v0 = yy[b];
        int k1 = k0 + 1;
        if (k1 < DX)            v1 = x[b * DX + k1];
        else if (k1 == DX)      v1 = tt[b];
        else if (k1 == DX + 1)  v1 = yy[b];
        zh[idx] = pack_h2(v0, v1);
    }
    __syncthreads();

    // ---- c partial sums: per-warp shfl reduce + 1 atomic/warp ----
    if (w < 4) {
        int j = t;   // 0..127
        float v = 0.0f;
        if (j < DN && j != DN - 2)
            v = sigm(Bp[(DN - 2) * DN + j]) * (1.0f + g_c_s[j]);
        #pragma unroll
        for (int off = 16; off > 0; off >>= 1)
            v += __shfl_xor_sync(0xFFFFFFFFu, v, off);
        if (lane == 0) atomicAdd(&accc[0], v);
        if (t == 0)
            atomicAdd(&accc[1],
                      sigm(Bp[(DN - 1) * DN + (DN - 2)]) * (1.0f + g_c_s[DN - 2]));
    }

    // ldmatrix per-lane base addresses (tile 0); tile 1 adds 16-row offset
    const int arow = lane & 15;
    const int acol = (lane >> 4) * 4;
    const uint32_t zh_a  = smem_u32(zh)  + (arow * ZSW + acol) * 4;
    const uint32_t r0h_a = smem_u32(r0h) + (arow * RSW + acol) * 4;
    const uint32_t ZT = 16 * ZSW * 4;     // tile stride in bytes
    const uint32_t RT = 16 * RSW * 4;

    const uint2* fB = g_fB + ((brB * 16 + wb_) * NCB) * 32 + lane;

    // stage-A bias (reused across tiles)
    const int h0A = 8 * w + 2 * qid;
    const float biA0 = bin[h0A], biA1 = bin[h0A + 1];

    // ---- early wB warm-up: first 4 chunks in flight across stage A ----
    uint2 wBp0 = __ldg(fB);
    uint2 wBp1 = __ldg(fB + 32);
    uint2 wBp2 = __ldg(fB + 64);
    uint2 wBp3 = __ldg(fB + 96);

    // ---- stage A: two 16-row tiles, ping-pong ldsm, dual accumulators ----
    #pragma unroll
    for (int tile = 0; tile < 2; tile++) {
        const uint32_t za = zh_a + tile * ZT;
        float accM[4], acc2[4];
        #pragma unroll
        for (int i = 0; i < 4; i++) { accM[i] = 0.0f; acc2[i] = 0.0f; }

        uint32_t fa[4], fbm[4];
        ldsm4(fa, za);
        #pragma unroll
        for (int g = 0; g < NCA; g++) {
            uint32_t* cur = (g & 1) ? fbm : fa;
            uint32_t* nxt = (g & 1) ? fa : fbm;
            if (g + 1 < NCA) ldsm4(nxt, za + (g + 1) * 32);
            mma16((g & 1) ? acc2 : accM, cur, wA[g].x, wA[g].y);
        }

        // epilogue: bias, relu, pack -> r0h[tile]
        float v00 = fmaxf(accM[0] + acc2[0] + biA0, 0.0f);
        float v01 = fmaxf(accM[1] + acc2[1] + biA1, 0.0f);
        float v10 = fmaxf(accM[2] + acc2[2] + biA0, 0.0f);
        float v11 = fmaxf(accM[3] + acc2[3] + biA1, 0.0f);
        int wofs = 4 * w + qid;
        r0h[(tile * 16 + grp) * RSW + wofs]     = pack_h2(v00, v01);
        r0h[(tile * 16 + grp + 8) * RSW + wofs] = pack_h2(v10, v11);
    }

    __syncthreads();   // r0 handoff (both tiles)

    // ---- stage-B epilogue constants ----
    const float* b1p = brB ? bY1 : bT1;
    const float* w2p = brB ? wY2 : wT2;
    const int h0 = 8 * wb_ + 2 * qid;
    const float b10 = b1p[h0], b11 = b1p[h0 + 1];
    const float w20 = w2p[h0], w21 = w2p[h0 + 1];
    const float cs  = 1.0f + g_c_s[DN - 2 + brB] + accc[brB] / (float)DN;

    // ---- stage B: two tiles; tile-1 weight reloads are L1 hits ----
    #pragma unroll
    for (int tile = 0; tile < 2; tile++) {
        const uint32_t ra = r0h_a + tile * RT;
        float accM[4], acc2[4];
        #pragma unroll
        for (int i = 0; i < 4; i++) { accM[i] = 0.0f; acc2[i] = 0.0f; }

        uint2 wB[NCB];
        if (tile == 0) {
            wB[0] = wBp0; wB[1] = wBp1; wB[2] = wBp2; wB[3] = wBp3;
        } else {
            #pragma unroll
            for (int j = 0; j < 4; j++) wB[j] = __ldg(fB + j * 32);  // L1 hits
        }

        uint32_t fa[4], fbm[4];
        ldsm4(fa, ra);
        #pragma unroll
        for (int j = 0; j < NCB; j++) {
            if (j + 4 < NCB) wB[j + 4] = __ldg(fB + (j + 4) * 32);
            uint32_t* cur = (j & 1) ? fbm : fa;
            uint32_t* nxt = (j & 1) ? fa : fbm;
            if (j + 1 < NCB) ldsm4(nxt, ra + (j + 1) * 32);
            mma16((j & 1) ? acc2 : accM, cur, wB[j].x, wB[j].y);
        }

        // epilogue: c-scale, bias, relu, dot w2, direct atomics
        float m, sl = 0.0f, sh = 0.0f;
        m = fmaxf(fmaf(cs, accM[0] + acc2[0], b10), 0.0f); sl = fmaf(m, w20, sl);
        m = fmaxf(fmaf(cs, accM[1] + acc2[1], b11), 0.0f); sl = fmaf(m, w21, sl);
        m = fmaxf(fmaf(cs, accM[2] + acc2[2], b10), 0.0f); sh = fmaf(m, w20, sh);
        m = fmaxf(fmaf(cs, accM[3] + acc2[3], b11), 0.0f); sh = fmaf(m, w21, sh);
        sl += __shfl_xor_sync(0xFFFFFFFFu, sl, 1);
        sl += __shfl_xor_sync(0xFFFFFFFFu, sl, 2);
        sh += __shfl_xor_sync(0xFFFFFFFFu, sh, 1);
        sh += __shfl_xor_sync(0xFFFFFFFFu, sh, 2);
        if (qid == 0) {
            atomicAdd(out + b0 + tile * 16 + grp,     sl);
            atomicAdd(out + b0 + tile * 16 + grp + 8, sh);
        }
    }
}

// ---------------------------------------------------------------------------
extern "C" void kernel_launch(void* const* d_in, const int* in_sizes, int n_in,
                              void* d_out, int out_size)
{
    const float* x    = (const float*)d_in[0];
    const float* tt   = (const float*)d_in[1];
    const float* yy   = (const float*)d_in[2];
    const float* Bprm = (const float*)d_in[3];
    const float* Win  = (const float*)d_in[4];
    const float* bin  = (const float*)d_in[5];
    const float* WT1  = (const float*)d_in[6];
    const float* bT1  = (const float*)d_in[7];
    const float* wT2  = (const float*)d_in[8];
    const float* bT2  = (const float*)d_in[9];
    const float* WY1  = (const float*)d_in[10];
    const float* bY1  = (const float*)d_in[11];
    const float* wY2  = (const float*)d_in[12];
    const float* bY2  = (const float*)d_in[13];
    float* out = (float*)d_out;

    prep_kernel<<<DN + PREP_FRAG_BLOCKS + PREP_OUT_BLOCKS, 128>>>(
        Bprm, Win, WT1, WY1, bT2, bY2, out);
    fused_kernel<<<NBLK, THREADS>>>(
        x, tt, yy, bin,
        bT1, wT2,
        bY1, wY2, Bprm, out);
}

// round 13
// speedup vs baseline: 1.2638x; 1.2638x over previous
#include <cuda_runtime.h>
#include <cuda_fp16.h>
#include <cstdint>

// ---------------------------------------------------------------------------
// GNN_EBM reduced form:
//   out[b] = MLP_T(c100 * r0[b]) + MLP_Y(c101 * r0[b]),
//   r0 = relu(z @ Win^T + bin),  z = [x|t|y], c_i from sigmoid(B)*mask rowsums.
//
// Round-13: revert R12's BT=32 regression (grid back to 128 = 1 block/SM,
// latency-bound => maximize chip parallelism). Add Programmatic Dependent
// Launch: fused starts while prep finishes; z-fill (prep-independent) runs
// before cudaGridDependencySynchronize(), weight reads after.
// ---------------------------------------------------------------------------

#define DX      100
#define DN      102
#define HID     256
#define MH      128
#define BT      16             // batch rows per block
#define NBLK    128
#define BATCH   2048
#define THREADS 1024
#define NCA     7              // stage-A chunks (16 k each)
#define NCB     16             // stage-B chunks

#define ZSW     60             // z row stride in 4B words (conflict-free ldsm)
#define RSW     132            // r0 row stride in words  (conflict-free ldsm)

#define NFRAG_A (32 * NCA * 32)     // 7168
#define NFRAG_B (32 * NCB * 32)     // 16384
#define PREP_FRAG_BLOCKS 184        // ceil((7168+16384)/128)
#define PREP_OUT_BLOCKS  (BATCH / 128)   // 16

__device__ float g_c_s[DN];                          // s[j] = rowsum_j(A)/N
__device__ __align__(16) uint2 g_fA[NFRAG_A];        // [tile][chunk][lane]
__device__ __align__(16) uint2 g_fB[NFRAG_B];        // [br*16+wb][chunk][lane]

__device__ __forceinline__ float sigm(float v) {
    return 1.0f / (1.0f + __expf(-v));
}

__device__ __forceinline__ void mma16(float* c, const uint32_t* a,
                                      uint32_t b0, uint32_t b1) {
    asm volatile(
        "mma.sync.aligned.m16n8k16.row.col.f32.f16.f16.f32 "
        "{%0,%1,%2,%3},{%4,%5,%6,%7},{%8,%9},{%0,%1,%2,%3};"
        : "+f"(c[0]), "+f"(c[1]), "+f"(c[2]), "+f"(c[3])
        : "r"(a[0]), "r"(a[1]), "r"(a[2]), "r"(a[3]), "r"(b0), "r"(b1));
}

__device__ __forceinline__ void ldsm4(uint32_t* r, uint32_t saddr) {
    asm volatile(
        "ldmatrix.sync.aligned.m8n8.x4.shared.b16 {%0,%1,%2,%3}, [%4];"
        : "=r"(r[0]), "=r"(r[1]), "=r"(r[2]), "=r"(r[3]) : "r"(saddr));
}

__device__ __forceinline__ uint32_t smem_u32(const void* p) {
    return (uint32_t)__cvta_generic_to_shared(p);
}

__device__ __forceinline__ uint32_t pack_h2(float v0, float v1) {
    __half2 h = __floats2half2_rn(v0, v1);   // cvt.rn.f16x2.f32
    return *reinterpret_cast<uint32_t*>(&h);
}

// ---------------------------------------------------------------------------
// K1 prep (302 blocks x 128 threads):
//   blocks 0..101  : g_c_s[b]
//   blocks 102..285: fragment-pack weights -> g_fA, g_fB
//   blocks 286..301: out[b] = bT2[0] + bY2[0]
// ---------------------------------------------------------------------------
__global__ __launch_bounds__(128) void prep_kernel(
    const float* __restrict__ B,   const float* __restrict__ Win,
    const float* __restrict__ WT1, const float* __restrict__ WY1,
    const float* __restrict__ bT2, const float* __restrict__ bY2,
    float* __restrict__ out)
{
    const int b = blockIdx.x;
    const int t = threadIdx.x;

    if (b < DN) {
        __shared__ float wsum[4];
        int k = t;
        float v = 0.0f;
        bool valid = (b == DN - 1) ? (k == DN - 2) : (k < DN && k != b);
        if (valid) v = sigm(B[b * DN + k]);
        #pragma unroll
        for (int off = 16; off > 0; off >>= 1)
            v += __shfl_xor_sync(0xFFFFFFFFu, v, off);
        if ((t & 31) == 0) wsum[t >> 5] = v;
        __syncthreads();
        if (t == 0)
            g_c_s[b] = (wsum[0] + wsum[1] + wsum[2] + wsum[3]) / (float)DN;
        return;
    }

    if (b >= DN + PREP_FRAG_BLOCKS) {
        int idx = (b - DN - PREP_FRAG_BLOCKS) * 128 + t;
        if (idx < BATCH) out[idx] = bT2[0] + bY2[0];
        return;
    }

    int fid = (b - DN) * 128 + t;
    if (fid < NFRAG_A) {
        int nt   = fid / (NCA * 32);
        int rem  = fid - nt * (NCA * 32);
        int g    = rem >> 5;
        int lane = rem & 31;
        int h  = 8 * nt + (lane >> 2);
        int k0 = 16 * g + 2 * (lane & 3);
        const float* wr = Win + h * DN;
        float v0 = (k0     < DN) ? wr[k0]     : 0.0f;
        float v1 = (k0 + 1 < DN) ? wr[k0 + 1] : 0.0f;
        float v2 = (k0 + 8 < DN) ? wr[k0 + 8] : 0.0f;
        float v3 = (k0 + 9 < DN) ? wr[k0 + 9] : 0.0f;
        uint2 o;
        o.x = pack_h2(v0, v1);
        o.y = pack_h2(v2, v3);
        g_fA[fid] = o;
        return;
    }

    int fid2 = fid - NFRAG_A;
    if (fid2 < NFRAG_B) {
        int tile = fid2 / (NCB * 32);   // br*16 + wb
        int rem  = fid2 - tile * (NCB * 32);
        int j    = rem >> 5;
        int lane = rem & 31;
        const float* W = (tile >> 4) ? WY1 : WT1;
        int h  = 8 * (tile & 15) + (lane >> 2);
        int k0 = 16 * j + 2 * (lane & 3);
        const float* wr = W + h * HID;
        uint2 o;
        o.x = pack_h2(wr[k0],     wr[k0 + 1]);
        o.y = pack_h2(wr[k0 + 8], wr[k0 + 9]);
        g_fB[fid2] = o;
    }
}

// ---------------------------------------------------------------------------
// K2 fused: 1024 threads (32 warps), BT=16 rows/block, PDL consumer.
// Warp w: stage A n-tile = cols [8w, 8w+8); stage B: branch w>>4, cols 8*(w&15).
// ---------------------------------------------------------------------------
__global__ __launch_bounds__(THREADS, 1) void fused_kernel(
    const float* __restrict__ x,   const float* __restrict__ tt,
    const float* __restrict__ yy,  const float* __restrict__ bin,
    const float* __restrict__ bT1, const float* __restrict__ wT2,
    const float* __restrict__ bY1, const float* __restrict__ wY2,
    const float* __restrict__ Bp,
    float* __restrict__ out)
{
    __shared__ __align__(16) uint32_t zh[BT * ZSW];
    __shared__ __align__(16) uint32_t r0h[BT * RSW];
    __shared__ float accc[2];

    const int t    = threadIdx.x;
    const int w    = t >> 5;
    const int lane = t & 31;
    const int grp  = lane >> 2;
    const int qid  = lane & 3;
    const int b0   = blockIdx.x * BT;

    const int brB = w >> 4;       // stage-B branch (0=T, 1=Y)
    const int wb_ = w & 15;

    if (t < 2) accc[t] = 0.0f;

    // ---- PDL phase 1: z-fill (independent of prep outputs) ----
    if (t < BT * ZSW) {           // 960 < 1024: one element per thread
        int r  = t / ZSW;
        int kw = t - r * ZSW;
        int b  = b0 + r;
        float v0 = 0.0f, v1 = 0.0f;
        int k0 = 2 * kw;
        if (k0 < DX)            v0 = x[b * DX + k0];
        else if (k0 == DX)      v0 = tt[b];
        else if (k0 == DX + 1)  v0 = yy[b];
        int k1 = k0 + 1;
        if (k1 < DX)            v1 = x[b * DX + k1];
        else if (k1 == DX)      v1 = tt[b];
        else if (k1 == DX + 1)  v1 = yy[b];
        zh[t] = pack_h2(v0, v1);
    }

    // ---- wait for prep's writes (g_fA/g_fB/g_c_s/out prefill) ----
    cudaGridDependencySynchronize();

    // ---- hoist stage-A weights into registers (7 x uint2) ----
    uint2 wA[NCA];
    {
        const uint2* fA = g_fA + (w * NCA) * 32 + lane;
        #pragma unroll
        for (int g = 0; g < NCA; g++) wA[g] = __ldg(fA + g * 32);
    }

    __syncthreads();   // z tile + accc init visible

    // ---- c partial sums: per-warp shfl reduce + 1 atomic/warp ----
    if (w < 4) {
        int j = t;   // 0..127
        float v = 0.0f;
        if (j < DN && j != DN - 2)
            v = sigm(Bp[(DN - 2) * DN + j]) * (1.0f + g_c_s[j]);
        #pragma unroll
        for (int off = 16; off > 0; off >>= 1)
            v += __shfl_xor_sync(0xFFFFFFFFu, v, off);
        if (lane == 0) atomicAdd(&accc[0], v);
        if (t == 0)
            atomicAdd(&accc[1],
                      sigm(Bp[(DN - 1) * DN + (DN - 2)]) * (1.0f + g_c_s[DN - 2]));
    }

    // ldmatrix per-lane source addresses
    const int arow = lane & 15;
    const int acol = (lane >> 4) * 4;
    const uint32_t zh_a  = smem_u32(zh)  + (arow * ZSW + acol) * 4;
    const uint32_t r0h_a = smem_u32(r0h) + (arow * RSW + acol) * 4;

    float accM[4], acc2[4];
    #pragma unroll
    for (int i = 0; i < 4; i++) { accM[i] = 0.0f; acc2[i] = 0.0f; }

    // ---- stage A: 7 chunks, ping-pong ldsm, dual accumulators ----
    {
        uint32_t fa[4], fb[4];
        ldsm4(fa, zh_a);
        #pragma unroll
        for (int g = 0; g < NCA; g++) {
            uint32_t* cur = (g & 1) ? fb : fa;
            uint32_t* nxt = (g & 1) ? fa : fb;
            if (g + 1 < NCA) ldsm4(nxt, zh_a + (g + 1) * 32);
            mma16((g & 1) ? acc2 : accM, cur, wA[g].x, wA[g].y);
        }
    }

    // ---- stage-B weights: rolling prefetch, distance 4 ----
    const uint2* fB = g_fB + ((brB * 16 + wb_) * NCB) * 32 + lane;
    uint2 wB[NCB];   // fully unrolled below -> ~5 live
    #pragma unroll
    for (int j = 0; j < 4; j++) wB[j] = __ldg(fB + j * 32);

    // stage-A epilogue: bias, relu, pack -> r0h
    {
        int h0 = 8 * w + 2 * qid;
        float bi0 = bin[h0], bi1 = bin[h0 + 1];
        float v00 = fmaxf(accM[0] + acc2[0] + bi0, 0.0f);
        float v01 = fmaxf(accM[1] + acc2[1] + bi1, 0.0f);
        float v10 = fmaxf(accM[2] + acc2[2] + bi0, 0.0f);
        float v11 = fmaxf(accM[3] + acc2[3] + bi1, 0.0f);
        int wofs = 4 * w + qid;
        r0h[grp * RSW + wofs]       = pack_h2(v00, v01);
        r0h[(grp + 8) * RSW + wofs] = pack_h2(v10, v11);
    }

    __syncthreads();   // r0 handoff

    #pragma unroll
    for (int i = 0; i < 4; i++) { accM[i] = 0.0f; acc2[i] = 0.0f; }

    // ---- stage B: 16 chunks, ping-pong ldsm, rolling weight prefetch ----
    {
        uint32_t fa[4], fb[4];
        ldsm4(fa, r0h_a);
        #pragma unroll
        for (int j = 0; j < NCB; j++) {
            if (j + 4 < NCB) wB[j + 4] = __ldg(fB + (j + 4) * 32);
            uint32_t* cur = (j & 1) ? fb : fa;
            uint32_t* nxt = (j & 1) ? fa : fb;
            if (j + 1 < NCB) ldsm4(nxt, r0h_a + (j + 1) * 32);
            mma16((j & 1) ? acc2 : accM, cur, wB[j].x, wB[j].y);
        }
    }

    // ---- stage-B epilogue: c-scale, bias, relu, dot w2, direct atomics ----
    {
        const float* b1p = brB ? bY1 : bT1;
        const float* w2p = brB ? wY2 : wT2;
        const float  cs  = 1.0f + g_c_s[DN - 2 + brB] + accc[brB] / (float)DN;

        int h0 = 8 * wb_ + 2 * qid;
        float b10 = b1p[h0], b11 = b1p[h0 + 1];
        float w20 = w2p[h0], w21 = w2p[h0 + 1];
        float m, sl = 0.0f, sh = 0.0f;
        m = fmaxf(fmaf(cs, accM[0] + acc2[0], b10), 0.0f); sl = fmaf(m, w20, sl);
        m = fmaxf(fmaf(cs, accM[1] + acc2[1], b11), 0.0f); sl = fmaf(m, w21, sl);
        m = fmaxf(fmaf(cs, accM[2] + acc2[2], b10), 0.0f); sh = fmaf(m, w20, sh);
        m = fmaxf(fmaf(cs, accM[3] + acc2[3], b11), 0.0f); sh = fmaf(m, w21, sh);
        sl += __shfl_xor_sync(0xFFFFFFFFu, sl, 1);
        sl += __shfl_xor_sync(0xFFFFFFFFu, sl, 2);
        sh += __shfl_xor_sync(0xFFFFFFFFu, sh, 1);
        sh += __shfl_xor_sync(0xFFFFFFFFu, sh, 2);
        if (qid == 0) {
            atomicAdd(out + b0 + grp,     sl);   // out prefilled with bT2+bY2
            atomicAdd(out + b0 + grp + 8, sh);
        }
    }
}

// ---------------------------------------------------------------------------
extern "C" void kernel_launch(void* const* d_in, const int* in_sizes, int n_in,
                              void* d_out, int out_size)
{
    const float* x    = (const float*)d_in[0];
    const float* tt   = (const float*)d_in[1];
    const float* yy   = (const float*)d_in[2];
    const float* Bprm = (const float*)d_in[3];
    const float* Win  = (const float*)d_in[4];
    const float* bin  = (const float*)d_in[5];
    const float* WT1  = (const float*)d_in[6];
    const float* bT1  = (const float*)d_in[7];
    const float* wT2  = (const float*)d_in[8];
    const float* bT2  = (const float*)d_in[9];
    const float* WY1  = (const float*)d_in[10];
    const float* bY1  = (const float*)d_in[11];
    const float* wY2  = (const float*)d_in[12];
    const float* bY2  = (const float*)d_in[13];
    float* out = (float*)d_out;

    prep_kernel<<<DN + PREP_FRAG_BLOCKS + PREP_OUT_BLOCKS, 128>>>(
        Bprm, Win, WT1, WY1, bT2, bY2, out);

    // PDL launch: fused may begin while prep drains; it synchronizes via
    // cudaGridDependencySynchronize() before touching prep outputs.
    cudaLaunchConfig_t cfg = {};
    cfg.gridDim  = dim3(NBLK, 1, 1);
    cfg.blockDim = dim3(THREADS, 1, 1);
    cfg.dynamicSmemBytes = 0;
    cfg.stream = 0;
    cudaLaunchAttribute attr[1];
    attr[0].id = cudaLaunchAttributeProgrammaticStreamSerialization;
    attr[0].val.programmaticStreamSerializationAllowed = 1;
    cfg.attrs = attr;
    cfg.numAttrs = 1;
    cudaLaunchKernelEx(&cfg, fused_kernel,
                       x, tt, yy, bin, bT1, wT2, bY1, wY2, Bprm, out);
}